// round 3
// baseline (speedup 1.0000x reference)
#include <cuda_runtime.h>
#include <cstdint>

#define NTOK 8192
#define DIM 256
#define EDIM 16
#define NCODE 8192
#define CHUNK 128                  // codes per dist block
#define NSPLIT (NCODE / CHUNK)     // 64
#define TOKS_PER_DBLK 1024         // 256 threads x 4 tokens

typedef unsigned long long ull;

__device__ int g_count;                 // zero-init; reset by k_fin each run
__device__ float4 g_proj4[NTOK * 4];    // [slot][16] floats, PRE-SCALED by -2
__device__ float g_logits[NCODE];
__device__ float g_lse;
__device__ ull g_key[NTOK];

__device__ __forceinline__ bool read_mask(const void* p, int i, int e4) {
    if (e4) return ((const int*)p)[i] != 0;       // int32 / float32 bool (bits != 0)
    return ((const unsigned char*)p)[i] != 0;     // uint8 bool
}

__device__ __forceinline__ ull pk2(float lo, float hi) {
    ull r;
    asm("mov.b64 %0, {%1, %2};" : "=l"(r) : "f"(lo), "f"(hi));
    return r;
}
__device__ __forceinline__ ull ffma2(ull a, ull b, ull c) {
    ull d;
    asm("fma.rn.f32x2 %0, %1, %2, %3;" : "=l"(d) : "l"(a), "l"(b), "l"(c));
    return d;
}
__device__ __forceinline__ ull fadd2(ull a, ull b) {
    ull d;
    asm("add.rn.f32x2 %0, %1, %2;" : "=l"(d) : "l"(a), "l"(b));
    return d;
}

// ================= Kernel 1: block-specialized front =================
// blocks [0,128):   LN + 16-dim projection, 4 threads/token, 64 tokens/block.
//                   Unmasked quads skip all work. Compaction via ballot+scan.
//                   Stores -2*proj (folds the distance scale into the operand).
// blocks [128,192): constant logits L[n] = mask_emb . W[:,n], 2-way D split.
__global__ void __launch_bounds__(256) k_front(const float* __restrict__ xs,
                                               const void* __restrict__ pad,
                                               const void* __restrict__ mm,
                                               const float* __restrict__ gamma,
                                               const float* __restrict__ beta,
                                               const float* __restrict__ P,
                                               const float* __restrict__ W,
                                               const float* __restrict__ me) {
    int tid = threadIdx.x;
    int bx = blockIdx.x;

    if (bx >= 128) {
        // ---- logits branch: 128 codes/block, 2 d-halves ----
        __shared__ float s_me[DIM];
        __shared__ float s_part[128];
        for (int i = tid; i < DIM; i += 256) s_me[i] = me[i];
        __syncthreads();
        int nl = tid & 127;
        int half = tid >> 7;
        int n = (bx - 128) * 128 + nl;
        int d0 = half * 128;
        float acc = 0.f;
#pragma unroll 8
        for (int d = 0; d < 128; d++)
            acc = fmaf(s_me[d0 + d], __ldg(&W[(size_t)(d0 + d) * NCODE + n]), acc);
        if (half == 1) s_part[nl] = acc;
        __syncthreads();
        if (half == 0) g_logits[n] = acc + s_part[nl];
        return;
    }

    // ---- LN + proj branch ----
    __shared__ float s_P[DIM * EDIM];
    __shared__ float s_g[DIM], s_b[DIM];
    __shared__ int s_wb[8];
    __shared__ int s_base;
    __shared__ int s_det;

    if (tid == 0) s_det = 0;
    for (int i = tid; i < DIM; i += 256) { s_g[i] = gamma[i]; s_b[i] = beta[i]; }
    for (int i = tid; i < DIM * EDIM / 4; i += 256)
        ((float4*)s_P)[i] = ((const float4*)P)[i];
    __syncthreads();

    // mask dtype detection (first 8192 bytes of masked_masks)
    {
        const unsigned* w = (const unsigned*)mm;
        int ni = 0, nf = 0;
        for (int i = tid; i < 2048; i += 256) {
            unsigned v = w[i];
            if (v != 0u && v != 1u) ni = 1;
            if (v != 0u && v != 0x3f800000u) nf = 1;
        }
        int fl = (ni ? 1 : 0) | (nf ? 2 : 0);
        if (fl) atomicOr(&s_det, fl);
    }
    __syncthreads();
    int e4 = (((s_det & 1) == 0) || ((s_det & 2) == 0)) ? 1 : 0;

    int tok = bx * 64 + (tid >> 2);       // 4 threads per token
    int q = tid & 3;
    int lane = tid & 31, wid = tid >> 5;
    bool m = read_mask(mm, tok, e4) && read_mask(pad, tok, e4);

    // compaction: one slot per masked token (quad leaders carry the bit)
    unsigned am = __ballot_sync(0xffffffffu, m);
    unsigned leaders = am & 0x11111111u;
    if (lane == 0) s_wb[wid] = __popc(leaders);
    __syncthreads();
    if (tid == 0) {
        int tot = 0;
#pragma unroll
        for (int i = 0; i < 8; i++) { int c = s_wb[i]; s_wb[i] = tot; tot += c; }
        s_base = atomicAdd(&g_count, tot);
    }
    __syncthreads();

    if (!m) return;
    int prefix = __popc(leaders & ((1u << (lane & ~3)) - 1));
    int slot = s_base + s_wb[wid] + prefix;

    // LN stats over my 64-element quarter
    const float4* x4 = (const float4*)(xs + (size_t)tok * DIM + q * 64);
    float sum = 0.f, sq = 0.f;
    float4 xv[16];
#pragma unroll
    for (int i = 0; i < 16; i++) {
        float4 v = x4[i];
        xv[i] = v;
        sum += (v.x + v.y) + (v.z + v.w);
        sq = fmaf(v.x, v.x, sq); sq = fmaf(v.y, v.y, sq);
        sq = fmaf(v.z, v.z, sq); sq = fmaf(v.w, v.w, sq);
    }
    sum += __shfl_xor_sync(am, sum, 1);
    sum += __shfl_xor_sync(am, sum, 2);
    sq  += __shfl_xor_sync(am, sq, 1);
    sq  += __shfl_xor_sync(am, sq, 2);
    float mu = sum * (1.f / DIM);
    float var = sq * (1.f / DIM) - mu * mu;
    float rstd = rsqrtf(var + 1e-5f);

    // projection partial over my 64 d's
    float proj[EDIM];
#pragma unroll
    for (int e = 0; e < EDIM; e++) proj[e] = 0.f;
    int dbase = q * 64;
#pragma unroll 4
    for (int i = 0; i < 16; i++) {
        float4 v = xv[i];
        int d = dbase + 4 * i;
        float h0 = (v.x - mu) * rstd * s_g[d + 0] + s_b[d + 0];
        float h1 = (v.y - mu) * rstd * s_g[d + 1] + s_b[d + 1];
        float h2 = (v.z - mu) * rstd * s_g[d + 2] + s_b[d + 2];
        float h3 = (v.w - mu) * rstd * s_g[d + 3] + s_b[d + 3];
#pragma unroll
        for (int e = 0; e < EDIM; e++) {
            float a = fmaf(h0, s_P[(d + 0) * EDIM + e],
                      fmaf(h1, s_P[(d + 1) * EDIM + e], 0.f));
            float b = fmaf(h2, s_P[(d + 2) * EDIM + e],
                      fmaf(h3, s_P[(d + 3) * EDIM + e], 0.f));
            proj[e] += a + b;
        }
    }
#pragma unroll
    for (int e = 0; e < EDIM; e++) {
        proj[e] += __shfl_xor_sync(am, proj[e], 1);
        proj[e] += __shfl_xor_sync(am, proj[e], 2);
    }

    if (q == 0) {
        float4* out = &g_proj4[slot * 4];
        out[0] = make_float4(-2.f * proj[0], -2.f * proj[1], -2.f * proj[2], -2.f * proj[3]);
        out[1] = make_float4(-2.f * proj[4], -2.f * proj[5], -2.f * proj[6], -2.f * proj[7]);
        out[2] = make_float4(-2.f * proj[8], -2.f * proj[9], -2.f * proj[10], -2.f * proj[11]);
        out[3] = make_float4(-2.f * proj[12], -2.f * proj[13], -2.f * proj[14], -2.f * proj[15]);
        g_key[slot] = ~0ull;
    }
}

// ========= Kernel 2: argmin over codebook (FFMA2, 4 tokens/thread) + lse =====
__global__ void __launch_bounds__(256) k_dist(const float* __restrict__ emb) {
    int tid = threadIdx.x;

    if (blockIdx.y == NSPLIT) {
        // ---- lse block (depends only on g_logits from k_front) ----
        if (blockIdx.x != 0) return;
        __shared__ float redf[8];
        __shared__ float s_bc;
        int lane = tid & 31, wid = tid >> 5;
        float m = -3.4e38f;
#pragma unroll
        for (int i = tid; i < NCODE; i += 256) m = fmaxf(m, g_logits[i]);
#pragma unroll
        for (int o = 16; o; o >>= 1) m = fmaxf(m, __shfl_xor_sync(0xffffffffu, m, o));
        if (lane == 0) redf[wid] = m;
        __syncthreads();
        if (tid == 0) {
            float v = redf[0];
#pragma unroll
            for (int i = 1; i < 8; i++) v = fmaxf(v, redf[i]);
            s_bc = v;
        }
        __syncthreads();
        float M = s_bc;
        float s = 0.f;
#pragma unroll
        for (int i = tid; i < NCODE; i += 256) s += expf(g_logits[i] - M);
#pragma unroll
        for (int o = 16; o; o >>= 1) s += __shfl_xor_sync(0xffffffffu, s, o);
        __syncthreads();
        if (lane == 0) redf[wid] = s;
        __syncthreads();
        if (tid == 0) {
            float v = 0.f;
#pragma unroll
            for (int i = 0; i < 8; i++) v += redf[i];
            g_lse = M + logf(v);
        }
        return;
    }

    int cnt = g_count;
    int tbase = blockIdx.x * TOKS_PER_DBLK;
    if (tbase >= cnt) return;

    __shared__ float s_ed[CHUNK * 32];   // each code: 16 values duplicated (ull pairs)
    __shared__ float s_sq[CHUNK * 2];    // |emb|^2 duplicated
    int nb = blockIdx.y * CHUNK;

    if (tid < CHUNK) {
        int n = nb + tid;
        float v[16]; float sq = 0.f;
#pragma unroll
        for (int e = 0; e < 16; e++) { v[e] = __ldg(&emb[e * NCODE + n]); sq = fmaf(v[e], v[e], sq); }
        float2* dd = (float2*)&s_ed[tid * 32];
#pragma unroll
        for (int e = 0; e < 16; e++) dd[e] = make_float2(v[e], v[e]);
        s_sq[2 * tid] = sq; s_sq[2 * tid + 1] = sq;
    }
    __syncthreads();

    int s0 = tbase + tid * 4;            // 4 tokens per thread
    const float4* pa = (const float4*)&g_proj4[(s0 + 0) * 4];
    const float4* pb = (const float4*)&g_proj4[(s0 + 1) * 4];
    const float4* pc = (const float4*)&g_proj4[(s0 + 2) * 4];
    const float4* pd = (const float4*)&g_proj4[(s0 + 3) * 4];

    ull ppA[16], ppB[16];
#pragma unroll
    for (int j = 0; j < 4; j++) {
        float4 a = pa[j], b = pb[j], c = pc[j], d = pd[j];
        ppA[4 * j + 0] = pk2(a.x, b.x); ppA[4 * j + 1] = pk2(a.y, b.y);
        ppA[4 * j + 2] = pk2(a.z, b.z); ppA[4 * j + 3] = pk2(a.w, b.w);
        ppB[4 * j + 0] = pk2(c.x, d.x); ppB[4 * j + 1] = pk2(c.y, d.y);
        ppB[4 * j + 2] = pk2(c.z, d.z); ppB[4 * j + 3] = pk2(c.w, d.w);
    }

    float best0 = 3.4e38f, best1 = 3.4e38f, best2 = 3.4e38f, best3 = 3.4e38f;
    int b0 = 0, b1 = 0, b2 = 0, b3 = 0;

#pragma unroll 2
    for (int i = 0; i < CHUNK; i++) {
        const longlong2* r8 = (const longlong2*)(s_ed + i * 32);
        ull sq2 = *(const ull*)(s_sq + 2 * i);
        ull a0 = sq2, a1 = 0ull, c0 = sq2, c1 = 0ull;  // dist = |e|^2 + (-2p).e
#pragma unroll
        for (int k = 0; k < 8; k++) {
            longlong2 qv = r8[k];
            a0 = ffma2(ppA[2 * k],     (ull)qv.x, a0);
            a1 = ffma2(ppA[2 * k + 1], (ull)qv.y, a1);
            c0 = ffma2(ppB[2 * k],     (ull)qv.x, c0);
            c1 = ffma2(ppB[2 * k + 1], (ull)qv.y, c1);
        }
        ull dA = fadd2(a0, a1);
        ull dB = fadd2(c0, c1);
        float f0 = __uint_as_float((unsigned)dA);
        float f1 = __uint_as_float((unsigned)(dA >> 32));
        float f2 = __uint_as_float((unsigned)dB);
        float f3 = __uint_as_float((unsigned)(dB >> 32));
        if (f0 < best0) { best0 = f0; b0 = i; }
        if (f1 < best1) { best1 = f1; b1 = i; }
        if (f2 < best2) { best2 = f2; b2 = i; }
        if (f3 < best3) { best3 = f3; b3 = i; }
    }

    float bests[4] = {best0, best1, best2, best3};
    int bidx[4] = {b0, b1, b2, b3};
#pragma unroll
    for (int j = 0; j < 4; j++) {
        if (s0 + j < cnt) {
            unsigned ub = __float_as_uint(bests[j]);
            unsigned mk = (ub & 0x80000000u) ? ~ub : (ub | 0x80000000u);
            atomicMin(&g_key[s0 + j], (((ull)mk) << 32) | (unsigned)(nb + bidx[j]));
        }
    }
}

// ================= Kernel 3: CE gather + finalize + reset =================
__global__ void __launch_bounds__(1024) k_fin(float* __restrict__ out, int n) {
    __shared__ double redd[32];
    int tid = threadIdx.x, lane = tid & 31, wid = tid >> 5;
    int cnt = g_count;

    double acc = 0.0;
    for (int slot = tid; slot < cnt; slot += 1024) {
        unsigned nidx = (unsigned)(g_key[slot] & 0xffffffffu);
        acc += (double)g_logits[nidx];
    }
#pragma unroll
    for (int o = 16; o; o >>= 1) acc += __shfl_xor_sync(0xffffffffu, acc, o);
    if (lane == 0) redd[wid] = acc;
    __syncthreads();
    if (tid == 0) {
        double t = 0.0;
#pragma unroll
        for (int i = 0; i < 32; i++) t += redd[i];
        float loss = (float)((double)g_lse - t / (double)cnt);   // C == 1
        for (int i = 0; i < n; i++) out[i] = loss;
        g_count = 0;   // reset for next graph replay
    }
}

extern "C" void kernel_launch(void* const* d_in, const int* in_sizes, int n_in,
                              void* d_out, int out_size) {
    (void)in_sizes; (void)n_in;
    const float* xs    = (const float*)d_in[0];
    const void*  pad   = d_in[1];
    const void*  mm    = d_in[2];
    const float* gamma = (const float*)d_in[3];
    const float* beta  = (const float*)d_in[4];
    const float* P     = (const float*)d_in[5];
    const float* emb   = (const float*)d_in[6];   // (1,16,8192)
    const float* W     = (const float*)d_in[7];   // (1,256,8192)
    const float* me    = (const float*)d_in[8];

    k_front<<<192, 256>>>(xs, pad, mm, gamma, beta, P, W, me);
    dim3 gd(NTOK / TOKS_PER_DBLK, NSPLIT + 1);    // 8 x 65 (y==64 -> lse block)
    k_dist<<<gd, 256>>>(emb);
    k_fin<<<1, 1024>>>((float*)d_out, out_size);
}

// round 4
// speedup vs baseline: 1.2022x; 1.2022x over previous
#include <cuda_runtime.h>
#include <cstdint>

#define NTOK 8192
#define DIM 256
#define EDIM 16
#define NCODE 8192
#define CHUNK 64                   // codes per dist block
#define NSPLIT (NCODE / CHUNK)     // 128
#define TOKS_PER_DBLK 1024         // 256 threads x 4 tokens
#define LN_BLOCKS 1024             // warp-per-token: 8 tokens/block
#define LG_BLOCKS 64

typedef unsigned long long ull;

__device__ int g_count;                 // zero-init; reset by k_fin each run
__device__ float4 g_proj4[NTOK * 4];    // [slot][16] floats, PRE-SCALED by -2
__device__ float g_logits[NCODE];
__device__ float g_lse;
__device__ ull g_key[NTOK];

__device__ __forceinline__ bool read_mask(const void* p, int i, int e4) {
    if (e4) return ((const int*)p)[i] != 0;       // int32 / float32 bool (bits != 0)
    return ((const unsigned char*)p)[i] != 0;     // uint8 bool
}

__device__ __forceinline__ ull pk2(float lo, float hi) {
    ull r;
    asm("mov.b64 %0, {%1, %2};" : "=l"(r) : "f"(lo), "f"(hi));
    return r;
}
__device__ __forceinline__ ull ffma2(ull a, ull b, ull c) {
    ull d;
    asm("fma.rn.f32x2 %0, %1, %2, %3;" : "=l"(d) : "l"(a), "l"(b), "l"(c));
    return d;
}
__device__ __forceinline__ ull fadd2(ull a, ull b) {
    ull d;
    asm("add.rn.f32x2 %0, %1, %2;" : "=l"(d) : "l"(a), "l"(b));
    return d;
}

// ================= Kernel 1: block-specialized front =================
// blocks [0,1024):       LN + projection, ONE WARP PER TOKEN (8 tokens/block).
// blocks [1024,1088):    constant logits L[n] = mask_emb . W[:,n].
__global__ void __launch_bounds__(256) k_front(const float* __restrict__ xs,
                                               const void* __restrict__ pad,
                                               const void* __restrict__ mm,
                                               const float* __restrict__ gamma,
                                               const float* __restrict__ beta,
                                               const float* __restrict__ P,
                                               const float* __restrict__ W,
                                               const float* __restrict__ me) {
    int tid = threadIdx.x;
    int bx = blockIdx.x;

    if (bx >= LN_BLOCKS) {
        // ---- logits branch: 128 codes/block, 2 d-halves ----
        __shared__ float s_me[DIM];
        __shared__ float s_part[128];
        for (int i = tid; i < DIM; i += 256) s_me[i] = me[i];
        __syncthreads();
        int nl = tid & 127;
        int half = tid >> 7;
        int n = (bx - LN_BLOCKS) * 128 + nl;
        int d0 = half * 128;
        float a0 = 0.f, a1 = 0.f;
#pragma unroll 8
        for (int d = 0; d < 128; d += 2) {
            a0 = fmaf(s_me[d0 + d],     __ldg(&W[(size_t)(d0 + d)     * NCODE + n]), a0);
            a1 = fmaf(s_me[d0 + d + 1], __ldg(&W[(size_t)(d0 + d + 1) * NCODE + n]), a1);
        }
        float acc = a0 + a1;
        if (half == 1) s_part[nl] = acc;
        __syncthreads();
        if (half == 0) g_logits[n] = acc + s_part[nl];
        return;
    }

    // ---- LN + projection branch (warp per token) ----
    __shared__ float s_P[DIM * 17];       // pitch 17: conflict-free lane-strided reads
    __shared__ float s_g[DIM], s_b[DIM];
    __shared__ int s_m[8];
    __shared__ int s_wb[8];
    __shared__ int s_base;
    __shared__ int s_det;

    int lane = tid & 31, wid = tid >> 5;
    if (tid == 0) s_det = 0;
    for (int i = tid; i < DIM; i += 256) { s_g[i] = gamma[i]; s_b[i] = beta[i]; }
    for (int i = tid; i < DIM * EDIM; i += 256) {
        int r = i >> 4, e = i & 15;
        s_P[r * 17 + e] = P[i];
    }
    // mask dtype detection (first 8192 bytes of masked_masks)
    {
        const unsigned* w = (const unsigned*)mm;
        int ni = 0, nf = 0;
        for (int i = tid; i < 2048; i += 256) {
            unsigned v = w[i];
            if (v != 0u && v != 1u) ni = 1;
            if (v != 0u && v != 0x3f800000u) nf = 1;
        }
        int fl = (ni ? 1 : 0) | (nf ? 2 : 0);
        if (fl) atomicOr(&s_det, fl);
    }
    __syncthreads();
    int e4 = (((s_det & 1) == 0) || ((s_det & 2) == 0)) ? 1 : 0;

    int tok = bx * 8 + wid;
    bool m;
    if (lane == 0) {
        m = read_mask(mm, tok, e4) && read_mask(pad, tok, e4);
        s_m[wid] = m ? 1 : 0;
    }
    __syncthreads();
    if (tid == 0) {
        int tot = 0;
#pragma unroll
        for (int i = 0; i < 8; i++) { int c = s_m[i]; s_wb[i] = tot; tot += c; }
        s_base = atomicAdd(&g_count, tot);
    }
    __syncthreads();
    if (!s_m[wid]) return;                // whole warp exits (token unmasked)
    int slot = s_base + s_wb[wid];

    // coalesced scalar loads: lane handles d = lane + 32*s
    const float* xp = xs + (size_t)tok * DIM + lane;
    float xv[8];
#pragma unroll
    for (int s = 0; s < 8; s++) xv[s] = xp[32 * s];

    float sum = 0.f, sq = 0.f;
#pragma unroll
    for (int s = 0; s < 8; s++) { sum += xv[s]; sq = fmaf(xv[s], xv[s], sq); }
#pragma unroll
    for (int o = 16; o; o >>= 1) {
        sum += __shfl_xor_sync(0xffffffffu, sum, o);
        sq  += __shfl_xor_sync(0xffffffffu, sq, o);
    }
    float mu = sum * (1.f / DIM);
    float var = sq * (1.f / DIM) - mu * mu;
    float rstd = rsqrtf(var + 1e-5f);

    float acc[EDIM];
#pragma unroll
    for (int e = 0; e < EDIM; e++) acc[e] = 0.f;
#pragma unroll
    for (int s = 0; s < 8; s++) {
        int d = lane + 32 * s;
        float h = (xv[s] - mu) * rstd * s_g[d] + s_b[d];
        const float* pr = &s_P[d * 17];
#pragma unroll
        for (int e = 0; e < EDIM; e++) acc[e] = fmaf(h, pr[e], acc[e]);
    }
#pragma unroll
    for (int e = 0; e < EDIM; e++) {
#pragma unroll
        for (int o = 16; o; o >>= 1) acc[e] += __shfl_xor_sync(0xffffffffu, acc[e], o);
    }

    if (lane == 0) {
        float4* out = &g_proj4[slot * 4];
        out[0] = make_float4(-2.f * acc[0],  -2.f * acc[1],  -2.f * acc[2],  -2.f * acc[3]);
        out[1] = make_float4(-2.f * acc[4],  -2.f * acc[5],  -2.f * acc[6],  -2.f * acc[7]);
        out[2] = make_float4(-2.f * acc[8],  -2.f * acc[9],  -2.f * acc[10], -2.f * acc[11]);
        out[3] = make_float4(-2.f * acc[12], -2.f * acc[13], -2.f * acc[14], -2.f * acc[15]);
        g_key[slot] = ~0ull;
    }
}

// ========= Kernel 2: argmin over codebook (FFMA2, 4 tokens/thread) + lse =====
__global__ void __launch_bounds__(256) k_dist(const float* __restrict__ emb) {
    int tid = threadIdx.x;

    if (blockIdx.y == NSPLIT) {
        // ---- lse block (depends only on g_logits from k_front) ----
        if (blockIdx.x != 0) return;
        __shared__ float redf[8];
        __shared__ float s_bc;
        int lane = tid & 31, wid = tid >> 5;
        float m = -3.4e38f;
#pragma unroll
        for (int i = tid; i < NCODE; i += 256) m = fmaxf(m, g_logits[i]);
#pragma unroll
        for (int o = 16; o; o >>= 1) m = fmaxf(m, __shfl_xor_sync(0xffffffffu, m, o));
        if (lane == 0) redf[wid] = m;
        __syncthreads();
        if (tid == 0) {
            float v = redf[0];
#pragma unroll
            for (int i = 1; i < 8; i++) v = fmaxf(v, redf[i]);
            s_bc = v;
        }
        __syncthreads();
        float M = s_bc;
        float s = 0.f;
#pragma unroll
        for (int i = tid; i < NCODE; i += 256) s += expf(g_logits[i] - M);
#pragma unroll
        for (int o = 16; o; o >>= 1) s += __shfl_xor_sync(0xffffffffu, s, o);
        __syncthreads();
        if (lane == 0) redf[wid] = s;
        __syncthreads();
        if (tid == 0) {
            float v = 0.f;
#pragma unroll
            for (int i = 0; i < 8; i++) v += redf[i];
            g_lse = M + logf(v);
        }
        return;
    }

    int cnt = g_count;
    int tbase = blockIdx.x * TOKS_PER_DBLK;
    if (tbase >= cnt) return;

    __shared__ float s_ed[CHUNK * 32];   // each code: 16 values duplicated (ull pairs)
    __shared__ float s_sq[CHUNK * 2];    // |emb|^2 duplicated
    int nb = blockIdx.y * CHUNK;

    if (tid < CHUNK) {
        int n = nb + tid;
        float v[16]; float sq = 0.f;
#pragma unroll
        for (int e = 0; e < 16; e++) { v[e] = __ldg(&emb[e * NCODE + n]); sq = fmaf(v[e], v[e], sq); }
        float2* dd = (float2*)&s_ed[tid * 32];
#pragma unroll
        for (int e = 0; e < 16; e++) dd[e] = make_float2(v[e], v[e]);
        s_sq[2 * tid] = sq; s_sq[2 * tid + 1] = sq;
    }
    __syncthreads();

    int s0 = tbase + tid * 4;            // 4 tokens per thread
    const float4* pa = (const float4*)&g_proj4[(s0 + 0) * 4];
    const float4* pb = (const float4*)&g_proj4[(s0 + 1) * 4];
    const float4* pc = (const float4*)&g_proj4[(s0 + 2) * 4];
    const float4* pd = (const float4*)&g_proj4[(s0 + 3) * 4];

    ull ppA[16], ppB[16];
#pragma unroll
    for (int j = 0; j < 4; j++) {
        float4 a = pa[j], b = pb[j], c = pc[j], d = pd[j];
        ppA[4 * j + 0] = pk2(a.x, b.x); ppA[4 * j + 1] = pk2(a.y, b.y);
        ppA[4 * j + 2] = pk2(a.z, b.z); ppA[4 * j + 3] = pk2(a.w, b.w);
        ppB[4 * j + 0] = pk2(c.x, d.x); ppB[4 * j + 1] = pk2(c.y, d.y);
        ppB[4 * j + 2] = pk2(c.z, d.z); ppB[4 * j + 3] = pk2(c.w, d.w);
    }

    float best0 = 3.4e38f, best1 = 3.4e38f, best2 = 3.4e38f, best3 = 3.4e38f;
    int b0 = 0, b1 = 0, b2 = 0, b3 = 0;

#pragma unroll 2
    for (int i = 0; i < CHUNK; i++) {
        const longlong2* r8 = (const longlong2*)(s_ed + i * 32);
        ull sq2 = *(const ull*)(s_sq + 2 * i);
        ull a0 = sq2, a1 = 0ull, c0 = sq2, c1 = 0ull;  // dist = |e|^2 + (-2p).e
#pragma unroll
        for (int k = 0; k < 8; k++) {
            longlong2 qv = r8[k];
            a0 = ffma2(ppA[2 * k],     (ull)qv.x, a0);
            a1 = ffma2(ppA[2 * k + 1], (ull)qv.y, a1);
            c0 = ffma2(ppB[2 * k],     (ull)qv.x, c0);
            c1 = ffma2(ppB[2 * k + 1], (ull)qv.y, c1);
        }
        ull dA = fadd2(a0, a1);
        ull dB = fadd2(c0, c1);
        float f0 = __uint_as_float((unsigned)dA);
        float f1 = __uint_as_float((unsigned)(dA >> 32));
        float f2 = __uint_as_float((unsigned)dB);
        float f3 = __uint_as_float((unsigned)(dB >> 32));
        if (f0 < best0) { best0 = f0; b0 = i; }
        if (f1 < best1) { best1 = f1; b1 = i; }
        if (f2 < best2) { best2 = f2; b2 = i; }
        if (f3 < best3) { best3 = f3; b3 = i; }
    }

    float bests[4] = {best0, best1, best2, best3};
    int bidx[4] = {b0, b1, b2, b3};
#pragma unroll
    for (int j = 0; j < 4; j++) {
        if (s0 + j < cnt) {
            unsigned ub = __float_as_uint(bests[j]);
            unsigned mk = (ub & 0x80000000u) ? ~ub : (ub | 0x80000000u);
            atomicMin(&g_key[s0 + j], (((ull)mk) << 32) | (unsigned)(nb + bidx[j]));
        }
    }
}

// ================= Kernel 3: CE gather + finalize + reset =================
__global__ void __launch_bounds__(1024) k_fin(float* __restrict__ out, int n) {
    __shared__ double redd[32];
    int tid = threadIdx.x, lane = tid & 31, wid = tid >> 5;
    int cnt = g_count;

    double acc = 0.0;
    for (int slot = tid; slot < cnt; slot += 1024) {
        unsigned nidx = (unsigned)(g_key[slot] & 0xffffffffu);
        acc += (double)g_logits[nidx];
    }
#pragma unroll
    for (int o = 16; o; o >>= 1) acc += __shfl_xor_sync(0xffffffffu, acc, o);
    if (lane == 0) redd[wid] = acc;
    __syncthreads();
    if (tid == 0) {
        double t = 0.0;
#pragma unroll
        for (int i = 0; i < 32; i++) t += redd[i];
        float loss = (float)((double)g_lse - t / (double)cnt);   // C == 1
        for (int i = 0; i < n; i++) out[i] = loss;
        g_count = 0;   // reset for next graph replay
    }
}

extern "C" void kernel_launch(void* const* d_in, const int* in_sizes, int n_in,
                              void* d_out, int out_size) {
    (void)in_sizes; (void)n_in;
    const float* xs    = (const float*)d_in[0];
    const void*  pad   = d_in[1];
    const void*  mm    = d_in[2];
    const float* gamma = (const float*)d_in[3];
    const float* beta  = (const float*)d_in[4];
    const float* P     = (const float*)d_in[5];
    const float* emb   = (const float*)d_in[6];   // (1,16,8192)
    const float* W     = (const float*)d_in[7];   // (1,256,8192)
    const float* me    = (const float*)d_in[8];

    k_front<<<LN_BLOCKS + LG_BLOCKS, 256>>>(xs, pad, mm, gamma, beta, P, W, me);
    dim3 gd(NTOK / TOKS_PER_DBLK, NSPLIT + 1);    // 8 x 129 (y==128 -> lse block)
    k_dist<<<gd, 256>>>(emb);
    k_fin<<<1, 1024>>>((float*)d_out, out_size);
}